// round 12
// baseline (speedup 1.0000x reference)
#include <cuda_runtime.h>
#include <cstdint>

// ---------------------------------------------------------------------------
// MoE experts, MXFP4 weights. E=8, D=H=2880, T=512, K=2, 90 groups/row.
// MEASURED ground truth (R11 diagnostic):
//   - in_sizes are ELEMENT counts; positional order as documented.
//   - hidden_states/routing_weights/biases: f32. router_indices: i32.
//   - gate_up_blocks/scales, down_blocks/scales: stored as INT32 words
//     (low byte = logical u8 value, upper 3 bytes zero).
//   - output: f32 [512,2880]. swiglu_limit = 7.
// ---------------------------------------------------------------------------

#define E_NUM   8
#define T_NUM   512
#define D_NUM   2880
#define H_NUM   2880
#define G_IN    90
#define ROWS_GU 5760
#define MAX_PAIRS (T_NUM * 2)
#define SWIGLU_LIMIT 7.0f

// ---- device scratch ----
__device__ int   g_cnt[E_NUM];
__device__ int   g_off[E_NUM];
__device__ int   g_tok[MAX_PAIRS];
__device__ float g_wt [MAX_PAIRS];
__device__ __align__(16) float g_act[(size_t)MAX_PAIRS * H_NUM]; // 11.8 MB

// ---------------------------------------------------------------------------
// MXFP4 e2m1 decode: mag {0,.5,1,1.5,2,3,4,6}, sign bit 3.
// ---------------------------------------------------------------------------
__device__ __forceinline__ float dec_nib(uint32_t n) {
    uint32_t mag = n & 7u;
    float v = (float)mag * 0.5f;
    if (mag >= 5u) v = (float)mag - 2.0f;
    if (mag == 7u) v = 6.0f;
    return (n & 8u) ? -v : v;
}

// decode 4 int32-stored block bytes (8 fp4 values) into dst[0..7], scaled
__device__ __forceinline__ void decode_i4(float* dst, int4 w, float scale) {
    int v[4] = {w.x, w.y, w.z, w.w};
#pragma unroll
    for (int j = 0; j < 4; j++) {
        uint32_t b = (uint32_t)v[j] & 0xFFu;
        dst[2 * j]     = dec_nib(b & 15u) * scale;
        dst[2 * j + 1] = dec_nib(b >> 4)  * scale;
    }
}

// ---------------------------------------------------------------------------
// K0: zero output
// ---------------------------------------------------------------------------
__global__ void k_zero(float4* __restrict__ out) {
    int i = blockIdx.x * blockDim.x + threadIdx.x;
    out[i] = make_float4(0.f, 0.f, 0.f, 0.f);
}

// ---------------------------------------------------------------------------
// K1: routing — per-expert token lists, compacted into global slots.
// ---------------------------------------------------------------------------
__global__ void k_route(const int* __restrict__ ri,
                        const float* __restrict__ rw) {
    __shared__ int cnt[E_NUM];
    __shared__ int cur[E_NUM];
    int t = threadIdx.x;
    if (t < E_NUM) cnt[t] = 0;
    __syncthreads();

    int e0 = 0, e1 = 0;
    float w0 = 0.f, w1 = 0.f;
    bool valid = t < T_NUM;
    if (valid) {
        e0 = ri[2 * t + 0] & 7;
        e1 = ri[2 * t + 1] & 7;
        w0 = rw[t * E_NUM + e0];
        w1 = rw[t * E_NUM + e1];
        atomicAdd(&cnt[e0], 1);
        if (e1 != e0) atomicAdd(&cnt[e1], 1);
    }
    __syncthreads();
    if (t == 0) {
        int acc = 0;
        for (int e = 0; e < E_NUM; e++) {
            cur[e] = acc; g_off[e] = acc; g_cnt[e] = cnt[e]; acc += cnt[e];
        }
    }
    __syncthreads();
    if (valid) {
        if (e0 == e1) {
            int s = atomicAdd(&cur[e0], 1);
            g_tok[s] = t;  g_wt[s] = w0 + w1;          // count=2 => 2*rw
        } else {
            int s = atomicAdd(&cur[e0], 1);
            g_tok[s] = t;  g_wt[s] = w0;
            s = atomicAdd(&cur[e1], 1);
            g_tok[s] = t;  g_wt[s] = w1;
        }
    }
}

// ---------------------------------------------------------------------------
// K2: gate_up GEMM (+bias) fused with SwiGLU -> g_act[slot][h]
// Block tile: 64 tokens x 64 w1-rows (32 h). Thread: 4 tok x 2 h x {g,l}.
// ---------------------------------------------------------------------------
__global__ __launch_bounds__(256) void k_gateup(
    const float* __restrict__ hs,
    const int*   __restrict__ gub,     // int32-stored block bytes
    const int*   __restrict__ gus,     // int32-stored scale bytes
    const float* __restrict__ gbias)
{
    const int e  = blockIdx.z;
    const int Ne = g_cnt[e];
    const int eb = g_off[e];
    const int t0 = blockIdx.y * 64;
    if (t0 >= Ne) return;
    const int r0 = blockIdx.x * 64;

    __shared__ float Xs[64][65];
    __shared__ float Ws[64][65];
    __shared__ int   stok[64];

    const int tid = threadIdx.x;
    if (tid < 64) {
        int slot = t0 + tid;
        stok[tid] = (slot < Ne) ? g_tok[eb + slot] : g_tok[eb];
    }
    __syncthreads();

    const int tx = tid & 15;
    const int ty = tid >> 4;

    float acc[16];
#pragma unroll
    for (int i = 0; i < 16; i++) acc[i] = 0.f;

    for (int kc = 0; kc < D_NUM; kc += 64) {
        // ---- activations: 64 tokens x 64 cols ----
#pragma unroll
        for (int j = 0; j < 4; j++) {
            int idx = tid + 256 * j;
            int tr  = idx >> 4;
            int c4  = idx & 15;
            const float4 v = *(const float4*)(hs + (size_t)stok[tr] * D_NUM + kc + c4 * 4);
            Xs[tr][c4 * 4 + 0] = v.x;
            Xs[tr][c4 * 4 + 1] = v.y;
            Xs[tr][c4 * 4 + 2] = v.z;
            Xs[tr][c4 * 4 + 3] = v.w;
        }
        // ---- weights: 64 rows x 2 groups; int32 storage, 16 int32/group ----
        {
            int part = tid & 1;             // 8-int32 half of the group
            int grp  = (tid >> 1) & 1;
            int row  = tid >> 2;
            size_t rowg = (size_t)(e * ROWS_GU + r0 + row) * G_IN + (kc >> 5) + grp;
            const int4* p = (const int4*)gub + rowg * 4 + part * 2;
            int4 wa = p[0], wb = p[1];
            float scale = __uint_as_float(((uint32_t)(gus[rowg] & 0xFF)) << 23);
            int cb = grp * 32 + part * 16;
            decode_i4(&Ws[row][cb],     wa, scale);
            decode_i4(&Ws[row][cb + 8], wb, scale);
        }
        __syncthreads();

#pragma unroll 8
        for (int k = 0; k < 64; k++) {
            float xr[4], wr[4];
#pragma unroll
            for (int m = 0; m < 4; m++) xr[m] = Xs[tx + 16 * m][k];
#pragma unroll
            for (int n = 0; n < 2; n++) {
                wr[2 * n]     = Ws[2 * (ty + 16 * n)][k];
                wr[2 * n + 1] = Ws[2 * (ty + 16 * n) + 1][k];
            }
#pragma unroll
            for (int m = 0; m < 4; m++)
#pragma unroll
                for (int n = 0; n < 2; n++) {
                    acc[(m * 2 + n) * 2 + 0] += xr[m] * wr[2 * n];
                    acc[(m * 2 + n) * 2 + 1] += xr[m] * wr[2 * n + 1];
                }
        }
        __syncthreads();
    }

    const float limit = SWIGLU_LIMIT;
    const float ALPHA = 1.702f;
#pragma unroll
    for (int m = 0; m < 4; m++) {
        int slot = t0 + tx + 16 * m;
        if (slot >= Ne) continue;
#pragma unroll
        for (int n = 0; n < 2; n++) {
            int h = (r0 >> 1) + ty + 16 * n;
            float g = acc[(m * 2 + n) * 2 + 0] + gbias[e * ROWS_GU + 2 * h];
            float l = acc[(m * 2 + n) * 2 + 1] + gbias[e * ROWS_GU + 2 * h + 1];
            g = fminf(g, limit);
            l = fminf(fmaxf(l, -limit), limit);
            float sg = 1.0f / (1.0f + __expf(-ALPHA * g));
            g_act[((size_t)eb + slot) * H_NUM + h] = g * sg * (l + 1.0f);
        }
    }
}

// ---------------------------------------------------------------------------
// K3: down GEMM (+bias), scaled by combine weight, atomicAdd into out.
// ---------------------------------------------------------------------------
__global__ __launch_bounds__(256) void k_down(
    const int*   __restrict__ dbk,     // int32-stored block bytes
    const int*   __restrict__ dsc,     // int32-stored scale bytes
    const float* __restrict__ dbias,
    float*       __restrict__ out)
{
    const int e  = blockIdx.z;
    const int Ne = g_cnt[e];
    const int eb = g_off[e];
    const int t0 = blockIdx.y * 64;
    if (t0 >= Ne) return;
    const int d0 = blockIdx.x * 64;

    __shared__ float As[64][65];
    __shared__ float Ws[64][65];
    __shared__ int   stok[64];
    __shared__ float swt[64];

    const int tid = threadIdx.x;
    if (tid < 64) {
        int slot  = t0 + tid;
        bool v    = slot < Ne;
        stok[tid] = v ? g_tok[eb + slot] : 0;
        swt[tid]  = v ? g_wt [eb + slot] : 0.f;
    }

    const int tx = tid & 15;
    const int ty = tid >> 4;

    float acc[16];
#pragma unroll
    for (int i = 0; i < 16; i++) acc[i] = 0.f;

    for (int kc = 0; kc < H_NUM; kc += 64) {
#pragma unroll
        for (int j = 0; j < 4; j++) {
            int idx = tid + 256 * j;
            int tr  = idx >> 4;
            int c4  = idx & 15;
            int slot = t0 + tr;
            if (slot >= Ne) slot = t0;
            const float4 v = *(const float4*)(g_act + ((size_t)eb + slot) * H_NUM + kc + c4 * 4);
            As[tr][c4 * 4 + 0] = v.x;
            As[tr][c4 * 4 + 1] = v.y;
            As[tr][c4 * 4 + 2] = v.z;
            As[tr][c4 * 4 + 3] = v.w;
        }
        {
            int part = tid & 1;
            int grp  = (tid >> 1) & 1;
            int row  = tid >> 2;
            size_t rowg = (size_t)(e * D_NUM + d0 + row) * G_IN + (kc >> 5) + grp;
            const int4* p = (const int4*)dbk + rowg * 4 + part * 2;
            int4 wa = p[0], wb = p[1];
            float scale = __uint_as_float(((uint32_t)(dsc[rowg] & 0xFF)) << 23);
            int cb = grp * 32 + part * 16;
            decode_i4(&Ws[row][cb],     wa, scale);
            decode_i4(&Ws[row][cb + 8], wb, scale);
        }
        __syncthreads();

#pragma unroll 8
        for (int k = 0; k < 64; k++) {
            float ar[4], wr[4];
#pragma unroll
            for (int m = 0; m < 4; m++) ar[m] = As[tx + 16 * m][k];
#pragma unroll
            for (int n = 0; n < 4; n++) wr[n] = Ws[ty + 16 * n][k];
#pragma unroll
            for (int m = 0; m < 4; m++)
#pragma unroll
                for (int n = 0; n < 4; n++)
                    acc[m * 4 + n] += ar[m] * wr[n];
        }
        __syncthreads();
    }

#pragma unroll
    for (int m = 0; m < 4; m++) {
        int lm   = tx + 16 * m;
        int slot = t0 + lm;
        if (slot >= Ne) continue;
        int   tok = stok[lm];
        float w   = swt[lm];
#pragma unroll
        for (int n = 0; n < 4; n++) {
            int d = d0 + ty + 16 * n;
            float val = w * (acc[m * 4 + n] + dbias[e * D_NUM + d]);
            atomicAdd(&out[(size_t)tok * D_NUM + d], val);
        }
    }
}

// ---------------------------------------------------------------------------
// launch (positional binding — confirmed by R11 diagnostic)
// ---------------------------------------------------------------------------
extern "C" void kernel_launch(void* const* d_in, const int* in_sizes, int n_in,
                              void* d_out, int out_size) {
    const float* hs    = (const float*)d_in[0];
    const int*   ri    = (const int*)  d_in[1];
    const float* rw    = (const float*)d_in[2];
    const int*   gub   = (const int*)  d_in[3];
    const int*   gus   = (const int*)  d_in[4];
    const float* gbias = (const float*)d_in[5];
    const int*   dbk   = (const int*)  d_in[6];
    const int*   dsc   = (const int*)  d_in[7];
    const float* dbias = (const float*)d_in[8];
    float*       out   = (float*)      d_out;

    k_zero<<<1440, 256>>>((float4*)out);
    k_route<<<1, 512>>>(ri, rw);
    k_gateup<<<dim3(90, 8, 8), 256>>>(hs, gub, gus, gbias);
    k_down<<<dim3(45, 8, 8), 256>>>(dbk, dsc, dbias, out);
}

// round 15
// speedup vs baseline: 3.4027x; 3.4027x over previous
#include <cuda_runtime.h>
#include <cuda_bf16.h>
#include <cstdint>

// ---------------------------------------------------------------------------
// MoE experts, MXFP4 weights — bf16 mma.sync (m16n8k16) implementation.
// Harness compiles for plain sm_100 (no tcgen05), so we use Ampere-style
// warp-level HMMA. Exact bf16 decode of MXFP4; activations split hi+lo bf16;
// both accumulate into the same fp32 accumulators (error ~1e-6).
// ---------------------------------------------------------------------------

#define E_NUM   8
#define T_NUM   512
#define D_NUM   2880
#define H_NUM   2880
#define G_IN    90
#define ROWS_GU 5760
#define MAX_PAIRS 1024
#define PADP    128
#define NCHUNK  45            // 2880 / 64
#define SWIGLU_LIMIT 7.0f
#define ALPHA   1.702f

#define AS      72            // smem row stride in bf16 elements
#define ASB     144           // row stride in bytes

// ---- device scratch ----
__device__ int   g_cnt[E_NUM];
__device__ int   g_off[E_NUM];
__device__ int   g_tok[MAX_PAIRS + PADP];
__device__ float g_wt [MAX_PAIRS + PADP];
__device__ __align__(16) uint16_t g_hs_hi[(size_t)T_NUM * D_NUM];
__device__ __align__(16) uint16_t g_hs_lo[(size_t)T_NUM * D_NUM];
__device__ __align__(16) uint16_t g_act_hi[(size_t)(MAX_PAIRS + PADP) * H_NUM];
__device__ __align__(16) uint16_t g_act_lo[(size_t)(MAX_PAIRS + PADP) * H_NUM];

// ---------------------------------------------------------------------------
// helpers
// ---------------------------------------------------------------------------
__device__ __forceinline__ uint32_t smem_u32(const void* p) {
    uint32_t a;
    asm("{ .reg .u64 t; cvta.to.shared.u64 t, %1; cvt.u32.u64 %0, t; }" : "=r"(a) : "l"(p));
    return a;
}
__device__ __forceinline__ void ldmx4(uint32_t* r, uint32_t addr) {
    asm volatile("ldmatrix.sync.aligned.m8n8.x4.shared.b16 {%0,%1,%2,%3}, [%4];"
        : "=r"(r[0]), "=r"(r[1]), "=r"(r[2]), "=r"(r[3]) : "r"(addr));
}
__device__ __forceinline__ void ldmx2(uint32_t* r, uint32_t addr) {
    asm volatile("ldmatrix.sync.aligned.m8n8.x2.shared.b16 {%0,%1}, [%2];"
        : "=r"(r[0]), "=r"(r[1]) : "r"(addr));
}
__device__ __forceinline__ void mma16816(float* c, const uint32_t* a, const uint32_t* b) {
    asm volatile(
        "mma.sync.aligned.m16n8k16.row.col.f32.bf16.bf16.f32 "
        "{%0,%1,%2,%3}, {%4,%5,%6,%7}, {%8,%9}, {%0,%1,%2,%3};"
        : "+f"(c[0]), "+f"(c[1]), "+f"(c[2]), "+f"(c[3])
        : "r"(a[0]), "r"(a[1]), "r"(a[2]), "r"(a[3]), "r"(b[0]), "r"(b[1]));
}
__device__ __forceinline__ float dec_nib(uint32_t n) {
    uint32_t mag = n & 7u;
    float v = (float)mag * 0.5f;
    if (mag >= 5u) v = (float)mag - 2.0f;
    if (mag == 7u) v = 6.0f;
    return (n & 8u) ? -v : v;
}
__device__ __forceinline__ uint32_t bf_bits(float x) {
    __nv_bfloat16 b = __float2bfloat16(x);
    return (uint32_t)*reinterpret_cast<uint16_t*>(&b);
}
__device__ __forceinline__ uint32_t mul_bf16x2(uint32_t a, uint32_t b) {
    uint32_t r;
    asm("mul.bf16x2 %0, %1, %2;" : "=r"(r) : "r"(a), "r"(b));
    return r;
}

// ---------------------------------------------------------------------------
// K0: zero output
// ---------------------------------------------------------------------------
__global__ void k_zero(float4* __restrict__ out) {
    int i = blockIdx.x * blockDim.x + threadIdx.x;
    out[i] = make_float4(0.f, 0.f, 0.f, 0.f);
}

// ---------------------------------------------------------------------------
// K1: routing
// ---------------------------------------------------------------------------
__global__ void k_route(const int* __restrict__ ri, const float* __restrict__ rw) {
    __shared__ int cnt[E_NUM];
    __shared__ int cur[E_NUM];
    int t = threadIdx.x;
    if (t < E_NUM) cnt[t] = 0;
    __syncthreads();
    int e0 = 0, e1 = 0; float w0 = 0.f, w1 = 0.f;
    bool valid = t < T_NUM;
    if (valid) {
        e0 = ri[2 * t] & 7; e1 = ri[2 * t + 1] & 7;
        w0 = rw[t * E_NUM + e0]; w1 = rw[t * E_NUM + e1];
        atomicAdd(&cnt[e0], 1);
        if (e1 != e0) atomicAdd(&cnt[e1], 1);
    }
    __syncthreads();
    if (t == 0) {
        int acc = 0;
        for (int e = 0; e < E_NUM; e++) {
            cur[e] = acc; g_off[e] = acc; g_cnt[e] = cnt[e]; acc += cnt[e];
        }
    }
    __syncthreads();
    if (valid) {
        if (e0 == e1) {
            int s = atomicAdd(&cur[e0], 1);
            g_tok[s] = t; g_wt[s] = w0 + w1;
        } else {
            int s = atomicAdd(&cur[e0], 1);
            g_tok[s] = t; g_wt[s] = w0;
            s = atomicAdd(&cur[e1], 1);
            g_tok[s] = t; g_wt[s] = w1;
        }
    }
}

// ---------------------------------------------------------------------------
// K2: hidden_states fp32 -> bf16 hi/lo
// ---------------------------------------------------------------------------
__global__ void k_cvt(const float* __restrict__ hs) {
    int i = blockIdx.x * blockDim.x + threadIdx.x;
    float x = hs[i];
    __nv_bfloat16 h = __float2bfloat16(x);
    float lo = x - __bfloat162float(h);
    __nv_bfloat16 l = __float2bfloat16(lo);
    g_hs_hi[i] = *reinterpret_cast<uint16_t*>(&h);
    g_hs_lo[i] = *reinterpret_cast<uint16_t*>(&l);
}

// ---------------------------------------------------------------------------
// K3: gate_up GEMM (+bias+SwiGLU) -> g_act_hi/lo
// Block: 128 slots x 64 w1-rows; 8 warps as 4(m) x 2(n); warp tile 32x32.
// ---------------------------------------------------------------------------
__global__ __launch_bounds__(256) void k_gu_mma(
    const int* __restrict__ gub, const int* __restrict__ gus,
    const float* __restrict__ gbias)
{
    const int e  = blockIdx.z;
    const int Ne = g_cnt[e];
    const int eb = g_off[e];
    const int t0 = blockIdx.y * 128;
    if (t0 >= Ne) return;
    const int r0 = blockIdx.x * 64;

    __shared__ __align__(16) uint16_t sA_hi[128 * AS];
    __shared__ __align__(16) uint16_t sA_lo[128 * AS];
    __shared__ __align__(16) uint16_t sB[64 * AS];
    __shared__ uint32_t s_lut[256];
    __shared__ int s_tok[128];

    const int tid  = threadIdx.x;
    const int wid  = tid >> 5;
    const int lane = tid & 31;
    const int warp_m = wid & 3;        // 0..3 -> 32-slot strip
    const int warp_n = wid >> 2;       // 0..1 -> 32-row strip

    if (tid < 256) s_lut[tid] = bf_bits(dec_nib(tid & 15u)) | (bf_bits(dec_nib(tid >> 4)) << 16);
    if (tid < 128) {
        int slot = t0 + tid;
        s_tok[tid] = (slot < Ne) ? g_tok[eb + slot] : g_tok[eb];
    }
    __syncthreads();

    const uint32_t sA_hi_u = smem_u32(sA_hi);
    const uint32_t sA_lo_u = smem_u32(sA_lo);
    const uint32_t sB_u    = smem_u32(sB);

    float acc[2][4][4];
#pragma unroll
    for (int i = 0; i < 2; i++)
#pragma unroll
        for (int j = 0; j < 4; j++)
#pragma unroll
            for (int k = 0; k < 4; k++) acc[i][j][k] = 0.f;

    // per-lane ldmatrix address offsets (bytes)
    const uint32_t a_row = (uint32_t)(lane & 15);
    const uint32_t a_koff = (uint32_t)(lane >> 4) * 16;      // 0 or 16 bytes
    const uint32_t b_row = (uint32_t)(lane & 7);
    const uint32_t b_koff = (uint32_t)((lane >> 3) & 1) * 16;

    for (int kc = 0; kc < NCHUNK; kc++) {
        // ---- A copy (hi+lo): 2048 x 16B ----
#pragma unroll
        for (int j = 0; j < 8; j++) {
            int idx = tid + j * 256;
            int til = idx >> 10;
            int r   = (idx >> 3) & 127;
            int c8  = idx & 7;
            const uint16_t* src = (til ? g_hs_lo : g_hs_hi)
                                  + (size_t)s_tok[r] * D_NUM + kc * 64 + c8 * 8;
            uint4 v = *(const uint4*)src;
            *(uint4*)((uint8_t*)(til ? sA_lo : sA_hi) + r * ASB + c8 * 16) = v;
        }
        // ---- B decode: 64 rows x 2 groups x 2 halves ----
        {
            int row = tid >> 2, sub = tid & 3, grp = sub >> 1, half = sub & 1;
            size_t rowg = (size_t)(e * ROWS_GU + r0 + row) * G_IN + kc * 2 + grp;
            const int4* p = (const int4*)gub + rowg * 4 + half * 2;
            int4 wa = p[0], wb = p[1];
            uint32_t s16 = ((uint32_t)gus[rowg] & 0xFF) << 7;
            uint32_t scale2 = s16 | (s16 << 16);
            uint32_t o[8];
            o[0] = mul_bf16x2(s_lut[(uint32_t)wa.x & 255], scale2);
            o[1] = mul_bf16x2(s_lut[(uint32_t)wa.y & 255], scale2);
            o[2] = mul_bf16x2(s_lut[(uint32_t)wa.z & 255], scale2);
            o[3] = mul_bf16x2(s_lut[(uint32_t)wa.w & 255], scale2);
            o[4] = mul_bf16x2(s_lut[(uint32_t)wb.x & 255], scale2);
            o[5] = mul_bf16x2(s_lut[(uint32_t)wb.y & 255], scale2);
            o[6] = mul_bf16x2(s_lut[(uint32_t)wb.z & 255], scale2);
            o[7] = mul_bf16x2(s_lut[(uint32_t)wb.w & 255], scale2);
            uint8_t* dst = (uint8_t*)sB + row * ASB + grp * 64 + half * 32;
            *(uint4*)dst        = make_uint4(o[0], o[1], o[2], o[3]);
            *(uint4*)(dst + 16) = make_uint4(o[4], o[5], o[6], o[7]);
        }
        __syncthreads();

        // ---- MMA over 4 k16 steps ----
#pragma unroll
        for (int ks = 0; ks < 4; ks++) {
            uint32_t bf[4][2];
#pragma unroll
            for (int ni = 0; ni < 4; ni++) {
                uint32_t addr = sB_u + (warp_n * 32 + ni * 8 + b_row) * ASB
                              + ks * 32 + b_koff;
                ldmx2(bf[ni], addr);
            }
#pragma unroll
            for (int mi = 0; mi < 2; mi++) {
                uint32_t ah[4], al[4];
                uint32_t ra = (warp_m * 32 + mi * 16 + a_row) * ASB + ks * 32 + a_koff;
                ldmx4(ah, sA_hi_u + ra);
                ldmx4(al, sA_lo_u + ra);
#pragma unroll
                for (int ni = 0; ni < 4; ni++) {
                    mma16816(acc[mi][ni], ah, bf[ni]);
                    mma16816(acc[mi][ni], al, bf[ni]);
                }
            }
        }
        __syncthreads();
    }

    // ---- epilogue: bias + SwiGLU -> act hi/lo (register-local pairs) ----
#pragma unroll
    for (int mi = 0; mi < 2; mi++) {
#pragma unroll
        for (int rr = 0; rr < 2; rr++) {
            int mrow = warp_m * 32 + mi * 16 + (lane >> 2) + rr * 8;
            int slot = t0 + mrow;
            if (slot >= Ne) continue;
#pragma unroll
            for (int ni = 0; ni < 4; ni++) {
                int col = r0 + warp_n * 32 + ni * 8 + (lane & 3) * 2;  // even
                float g = acc[mi][ni][rr * 2 + 0] + gbias[e * ROWS_GU + col];
                float l = acc[mi][ni][rr * 2 + 1] + gbias[e * ROWS_GU + col + 1];
                g = fminf(g, SWIGLU_LIMIT);
                l = fminf(fmaxf(l, -SWIGLU_LIMIT), SWIGLU_LIMIT);
                float sig = 1.0f / (1.0f + __expf(-ALPHA * g));
                float a = g * sig * (l + 1.0f);
                __nv_bfloat16 h = __float2bfloat16(a);
                float lo = a - __bfloat162float(h);
                __nv_bfloat16 lb = __float2bfloat16(lo);
                size_t oidx = (size_t)(eb + slot) * H_NUM + (col >> 1);
                g_act_hi[oidx] = *reinterpret_cast<uint16_t*>(&h);
                g_act_lo[oidx] = *reinterpret_cast<uint16_t*>(&lb);
            }
        }
    }
}

// ---------------------------------------------------------------------------
// K4: down GEMM (+bias, combine weight) -> atomicAdd out
// ---------------------------------------------------------------------------
__global__ __launch_bounds__(256) void k_dn_mma(
    const int* __restrict__ dbk, const int* __restrict__ dsc,
    const float* __restrict__ dbias, float* __restrict__ out)
{
    const int e  = blockIdx.z;
    const int Ne = g_cnt[e];
    const int eb = g_off[e];
    const int t0 = blockIdx.y * 128;
    if (t0 >= Ne) return;
    const int d0 = blockIdx.x * 64;

    __shared__ __align__(16) uint16_t sA_hi[128 * AS];
    __shared__ __align__(16) uint16_t sA_lo[128 * AS];
    __shared__ __align__(16) uint16_t sB[64 * AS];
    __shared__ uint32_t s_lut[256];
    __shared__ int   s_tok[128];
    __shared__ float s_wtt[128];

    const int tid  = threadIdx.x;
    const int wid  = tid >> 5;
    const int lane = tid & 31;
    const int warp_m = wid & 3;
    const int warp_n = wid >> 2;

    if (tid < 256) s_lut[tid] = bf_bits(dec_nib(tid & 15u)) | (bf_bits(dec_nib(tid >> 4)) << 16);
    if (tid < 128) {
        int slot = t0 + tid;
        bool v = slot < Ne;
        s_tok[tid] = v ? g_tok[eb + slot] : 0;
        s_wtt[tid] = v ? g_wt [eb + slot] : 0.f;
    }
    __syncthreads();

    const uint32_t sA_hi_u = smem_u32(sA_hi);
    const uint32_t sA_lo_u = smem_u32(sA_lo);
    const uint32_t sB_u    = smem_u32(sB);

    float acc[2][4][4];
#pragma unroll
    for (int i = 0; i < 2; i++)
#pragma unroll
        for (int j = 0; j < 4; j++)
#pragma unroll
            for (int k = 0; k < 4; k++) acc[i][j][k] = 0.f;

    const uint32_t a_row = (uint32_t)(lane & 15);
    const uint32_t a_koff = (uint32_t)(lane >> 4) * 16;
    const uint32_t b_row = (uint32_t)(lane & 7);
    const uint32_t b_koff = (uint32_t)((lane >> 3) & 1) * 16;

    for (int kc = 0; kc < NCHUNK; kc++) {
#pragma unroll
        for (int j = 0; j < 8; j++) {
            int idx = tid + j * 256;
            int til = idx >> 10;
            int r   = (idx >> 3) & 127;
            int c8  = idx & 7;
            const uint16_t* src = (til ? g_act_lo : g_act_hi)
                                  + (size_t)(eb + t0 + r) * H_NUM + kc * 64 + c8 * 8;
            uint4 v = *(const uint4*)src;
            *(uint4*)((uint8_t*)(til ? sA_lo : sA_hi) + r * ASB + c8 * 16) = v;
        }
        {
            int row = tid >> 2, sub = tid & 3, grp = sub >> 1, half = sub & 1;
            size_t rowg = (size_t)(e * D_NUM + d0 + row) * G_IN + kc * 2 + grp;
            const int4* p = (const int4*)dbk + rowg * 4 + half * 2;
            int4 wa = p[0], wb = p[1];
            uint32_t s16 = ((uint32_t)dsc[rowg] & 0xFF) << 7;
            uint32_t scale2 = s16 | (s16 << 16);
            uint32_t o[8];
            o[0] = mul_bf16x2(s_lut[(uint32_t)wa.x & 255], scale2);
            o[1] = mul_bf16x2(s_lut[(uint32_t)wa.y & 255], scale2);
            o[2] = mul_bf16x2(s_lut[(uint32_t)wa.z & 255], scale2);
            o[3] = mul_bf16x2(s_lut[(uint32_t)wa.w & 255], scale2);
            o[4] = mul_bf16x2(s_lut[(uint32_t)wb.x & 255], scale2);
            o[5] = mul_bf16x2(s_lut[(uint32_t)wb.y & 255], scale2);
            o[6] = mul_bf16x2(s_lut[(uint32_t)wb.z & 255], scale2);
            o[7] = mul_bf16x2(s_lut[(uint32_t)wb.w & 255], scale2);
            uint8_t* dst = (uint8_t*)sB + row * ASB + grp * 64 + half * 32;
            *(uint4*)dst        = make_uint4(o[0], o[1], o[2], o[3]);
            *(uint4*)(dst + 16) = make_uint4(o[4], o[5], o[6], o[7]);
        }
        __syncthreads();

#pragma unroll
        for (int ks = 0; ks < 4; ks++) {
            uint32_t bf[4][2];
#pragma unroll
            for (int ni = 0; ni < 4; ni++) {
                uint32_t addr = sB_u + (warp_n * 32 + ni * 8 + b_row) * ASB
                              + ks * 32 + b_koff;
                ldmx2(bf[ni], addr);
            }
#pragma unroll
            for (int mi = 0; mi < 2; mi++) {
                uint32_t ah[4], al[4];
                uint32_t ra = (warp_m * 32 + mi * 16 + a_row) * ASB + ks * 32 + a_koff;
                ldmx4(ah, sA_hi_u + ra);
                ldmx4(al, sA_lo_u + ra);
#pragma unroll
                for (int ni = 0; ni < 4; ni++) {
                    mma16816(acc[mi][ni], ah, bf[ni]);
                    mma16816(acc[mi][ni], al, bf[ni]);
                }
            }
        }
        __syncthreads();
    }

    // ---- epilogue: bias + combine weight -> atomicAdd ----
#pragma unroll
    for (int mi = 0; mi < 2; mi++) {
#pragma unroll
        for (int rr = 0; rr < 2; rr++) {
            int mrow = warp_m * 32 + mi * 16 + (lane >> 2) + rr * 8;
            int slot = t0 + mrow;
            if (slot >= Ne) continue;
            int   tok = s_tok[mrow];
            float w   = s_wtt[mrow];
#pragma unroll
            for (int ni = 0; ni < 4; ni++) {
                int d = d0 + warp_n * 32 + ni * 8 + (lane & 3) * 2;
                float y0 = acc[mi][ni][rr * 2 + 0] + dbias[e * D_NUM + d];
                float y1 = acc[mi][ni][rr * 2 + 1] + dbias[e * D_NUM + d + 1];
                atomicAdd(&out[(size_t)tok * D_NUM + d],     w * y0);
                atomicAdd(&out[(size_t)tok * D_NUM + d + 1], w * y1);
            }
        }
    }
}

// ---------------------------------------------------------------------------
// launch
// ---------------------------------------------------------------------------
extern "C" void kernel_launch(void* const* d_in, const int* in_sizes, int n_in,
                              void* d_out, int out_size) {
    const float* hs    = (const float*)d_in[0];
    const int*   ri    = (const int*)  d_in[1];
    const float* rw    = (const float*)d_in[2];
    const int*   gub   = (const int*)  d_in[3];
    const int*   gus   = (const int*)  d_in[4];
    const float* gbias = (const float*)d_in[5];
    const int*   dbk   = (const int*)  d_in[6];
    const int*   dsc   = (const int*)  d_in[7];
    const float* dbias = (const float*)d_in[8];
    float*       out   = (float*)      d_out;

    k_zero<<<1440, 256>>>((float4*)out);
    k_route<<<1, 512>>>(ri, rw);
    k_cvt<<<5760, 256>>>(hs);
    k_gu_mma<<<dim3(90, 4, 8), 256>>>(gub, gus, gbias);
    k_dn_mma<<<dim3(45, 4, 8), 256>>>(dbk, dsc, dbias, out);
}